// round 1
// baseline (speedup 1.0000x reference)
#include <cuda_runtime.h>
#include <cstdint>

#define NSYMS  256
#define NSTEPS 8192
#define NCH    62
#define NOUT   64
#define HID    16

// Effective combined weight, layout [cin][o]: g_W[cin*64 + o] = (W3@W2@W1)[o][cin]
__device__ float g_W[64 * 64];

// ---------------------------------------------------------------------------
// Kernel 1: build W_eff = W3 @ W2 @ W1  (tiny; one block)
// ---------------------------------------------------------------------------
__global__ void build_weff(const float* __restrict__ W1h, const float* __restrict__ M1h,
                           const float* __restrict__ W2h, const float* __restrict__ M2h,
                           const float* __restrict__ W3h, const float* __restrict__ M3h) {
    __shared__ float W1[HID * 64];   // 16 x 64
    __shared__ float W2[HID * HID];  // 16 x 16
    __shared__ float W3[64 * HID];   // 64 x 16
    __shared__ float T2[HID * 64];   // W2 @ W1 : 16 x 64
    const int tid = threadIdx.x;

    for (int i = tid; i < HID * 64; i += 256)
        W1[i] = tanhf(W1h[i]) * (1.0f / (1.0f + expf(-M1h[i])));
    for (int i = tid; i < HID * HID; i += 256)
        W2[i] = tanhf(W2h[i]) * (1.0f / (1.0f + expf(-M2h[i])));
    for (int i = tid; i < 64 * HID; i += 256)
        W3[i] = tanhf(W3h[i]) * (1.0f / (1.0f + expf(-M3h[i])));
    __syncthreads();

    // T2[h][c] = sum_k W2[h][k] * W1[k][c]
    for (int i = tid; i < HID * 64; i += 256) {
        int h = i >> 6, c = i & 63;
        float s = 0.0f;
#pragma unroll
        for (int k = 0; k < HID; k++) s += W2[h * HID + k] * W1[k * 64 + c];
        T2[i] = s;
    }
    __syncthreads();

    // Weff[o][c] = sum_k W3[o][k] * T2[k][c]; store transposed [c][o]
    for (int i = tid; i < 64 * 64; i += 256) {
        int o = i >> 6, c = i & 63;
        float s = 0.0f;
#pragma unroll
        for (int k = 0; k < HID; k++) s += W3[o * HID + k] * T2[k * 64 + c];
        g_W[c * 64 + o] = s;
    }
}

// ---------------------------------------------------------------------------
// Packed fp32x2 helpers (FFMA2 path — only reachable via PTX on sm_103a)
// ---------------------------------------------------------------------------
__device__ __forceinline__ unsigned long long fma2(unsigned long long a,
                                                   unsigned long long b,
                                                   unsigned long long c) {
    unsigned long long d;
    asm("fma.rn.f32x2 %0, %1, %2, %3;" : "=l"(d) : "l"(a), "l"(b), "l"(c));
    return d;
}
__device__ __forceinline__ unsigned long long pack2(float lo, float hi) {
    unsigned long long r;
    asm("mov.b64 %0, {%1, %2};" : "=l"(r) : "f"(lo), "f"(hi));
    return r;
}
__device__ __forceinline__ void unpack2(unsigned long long v, float& lo, float& hi) {
    asm("mov.b64 {%0, %1}, %2;" : "=f"(lo), "=f"(hi) : "l"(v));
}

// ---------------------------------------------------------------------------
// Kernel 2: out[r][o] = Weff[o][0]*s + Weff[o][1]*t + sum_c Weff[o][c+2]*m[r][c]
//   128 rows/block, 256 threads; thread tile = 4 rows x 8 outs,
//   rows paired into f32x2 lanes.
// ---------------------------------------------------------------------------
#define ROWS_BLK 128
#define TPB      256
#define XSTRIDE  130   // even -> 8B-aligned f32x2 loads; not mult of 32 -> banks spread
#define SMEM_BYTES (64 * 64 * 2 * 4 + NCH * XSTRIDE * 4)  // 32768 + 32240 = 65008

__global__ void __launch_bounds__(TPB)
encode_kernel(const float* __restrict__ market, float* __restrict__ out) {
    extern __shared__ float sm[];
    float2* sw = (float2*)sm;               // [64 cin][64 o], each entry duplicated (w,w)
    float*  sx = sm + 64 * 64 * 2;          // [62 c][130 pad] transposed market tile

    const long long row0 = (long long)blockIdx.x * ROWS_BLK;
    const float* src = market + row0 * NCH;

    // stage W (duplicated pairs) and transposed market tile
    for (int i = threadIdx.x; i < 64 * 64; i += TPB) {
        float w = g_W[i];
        sw[i] = make_float2(w, w);
    }
    for (int i = threadIdx.x; i < ROWS_BLK * NCH; i += TPB) {   // 31 exact iters
        int r = i / NCH;
        int c = i - r * NCH;
        sx[c * XSTRIDE + r] = src[i];
    }
    __syncthreads();

    const int og = threadIdx.x & 7;     // 8 output groups
    const int rg = threadIdx.x >> 3;    // 32 row groups
    const int o0 = og << 3;             // 8 outputs per thread
    const int r0 = rg << 2;             // 4 rows per thread (2 f32x2 pairs)

    // block never crosses a symbol boundary (8192 % 128 == 0)
    const float fs  = (float)(row0 >> 13);
    const float ft0 = (float)((int)(row0 & (NSTEPS - 1)) + r0);

    unsigned long long acc0[8], acc1[8];
#pragma unroll
    for (int j = 0; j < 8; j++) {
        float a = sw[o0 + j].x;          // cin = 0 (symbol)
        float b = sw[64 + o0 + j].x;     // cin = 1 (t)
        float base = a * fs;
        acc0[j] = pack2(base + b * ft0,          base + b * (ft0 + 1.0f));
        acc1[j] = pack2(base + b * (ft0 + 2.0f), base + b * (ft0 + 3.0f));
    }

    // market channels map to cin = 2..63
    const unsigned long long* wbase = (const unsigned long long*)(sw + 2 * 64);

#pragma unroll 4
    for (int c = 0; c < NCH; c++) {
        unsigned long long x01 = *(const unsigned long long*)(sx + c * XSTRIDE + r0);
        unsigned long long x23 = *(const unsigned long long*)(sx + c * XSTRIDE + r0 + 2);
        const unsigned long long* wp = wbase + c * 64 + o0;
#pragma unroll
        for (int j = 0; j < 8; j++) {
            unsigned long long w = wp[j];
            acc0[j] = fma2(x01, w, acc0[j]);
            acc1[j] = fma2(x23, w, acc1[j]);
        }
    }

    // store: 4 rows x 8 consecutive outs; lanes of a warp cover 256B per row
    float* orow = out + (row0 + r0) * 64 + o0;
#pragma unroll
    for (int j = 0; j < 8; j++) {
        float v0, v1, v2, v3;
        unpack2(acc0[j], v0, v1);
        unpack2(acc1[j], v2, v3);
        orow[j]           = v0;
        orow[64 + j]      = v1;
        orow[128 + j]     = v2;
        orow[192 + j]     = v3;
    }
}

// ---------------------------------------------------------------------------
extern "C" void kernel_launch(void* const* d_in, const int* in_sizes, int n_in,
                              void* d_out, int out_size) {
    const float* market = (const float*)d_in[0];
    build_weff<<<1, 256>>>((const float*)d_in[1], (const float*)d_in[2],
                           (const float*)d_in[3], (const float*)d_in[4],
                           (const float*)d_in[5], (const float*)d_in[6]);

    cudaFuncSetAttribute((const void*)encode_kernel,
                         cudaFuncAttributeMaxDynamicSharedMemorySize, SMEM_BYTES);
    const int nblocks = (NSYMS * NSTEPS) / ROWS_BLK;  // 16384
    encode_kernel<<<nblocks, TPB, SMEM_BYTES>>>(market, (float*)d_out);
}

// round 2
// speedup vs baseline: 3.1883x; 3.1883x over previous
#include <cuda_runtime.h>
#include <cstdint>

#define NSYMS  256
#define NSTEPS 8192
#define NCH    62
#define NOUT   64
#define HID    16

// Effective combined weight, layout [cin][o]: g_W[cin*64 + o] = (W3@W2@W1)[o][cin]
__device__ float g_W[64 * 64];

// ---------------------------------------------------------------------------
// Kernel 1: build W_eff = W3 @ W2 @ W1  (tiny; one block)
// ---------------------------------------------------------------------------
__global__ void build_weff(const float* __restrict__ W1h, const float* __restrict__ M1h,
                           const float* __restrict__ W2h, const float* __restrict__ M2h,
                           const float* __restrict__ W3h, const float* __restrict__ M3h) {
    __shared__ float W1[HID * 64];
    __shared__ float W2[HID * HID];
    __shared__ float W3[64 * HID];
    __shared__ float T2[HID * 64];
    const int tid = threadIdx.x;

    for (int i = tid; i < HID * 64; i += 256)
        W1[i] = tanhf(W1h[i]) * (1.0f / (1.0f + expf(-M1h[i])));
    for (int i = tid; i < HID * HID; i += 256)
        W2[i] = tanhf(W2h[i]) * (1.0f / (1.0f + expf(-M2h[i])));
    for (int i = tid; i < 64 * HID; i += 256)
        W3[i] = tanhf(W3h[i]) * (1.0f / (1.0f + expf(-M3h[i])));
    __syncthreads();

    for (int i = tid; i < HID * 64; i += 256) {
        int h = i >> 6, c = i & 63;
        float s = 0.0f;
#pragma unroll
        for (int k = 0; k < HID; k++) s += W2[h * HID + k] * W1[k * 64 + c];
        T2[i] = s;
    }
    __syncthreads();

    for (int i = tid; i < 64 * 64; i += 256) {
        int o = i >> 6, c = i & 63;
        float s = 0.0f;
#pragma unroll
        for (int k = 0; k < HID; k++) s += W3[o * HID + k] * T2[k * 64 + c];
        g_W[c * 64 + o] = s;
    }
}

// ---------------------------------------------------------------------------
// Packed fp32x2 helpers
// ---------------------------------------------------------------------------
__device__ __forceinline__ unsigned long long fma2(unsigned long long a,
                                                   unsigned long long b,
                                                   unsigned long long c) {
    unsigned long long d;
    asm("fma.rn.f32x2 %0, %1, %2, %3;" : "=l"(d) : "l"(a), "l"(b), "l"(c));
    return d;
}
__device__ __forceinline__ unsigned long long pack2(float lo, float hi) {
    unsigned long long r;
    asm("mov.b64 %0, {%1, %2};" : "=l"(r) : "f"(lo), "f"(hi));
    return r;
}
__device__ __forceinline__ void unpack2(unsigned long long v, float& lo, float& hi) {
    asm("mov.b64 {%0, %1}, %2;" : "=f"(lo), "=f"(hi) : "l"(v));
}

// ---------------------------------------------------------------------------
// Kernel 2: warp = output group (weights broadcast), lanes = row groups.
//   Block: 256 threads = 8 warps, 128 rows.
//   Warp w handles outputs [w*8, w*8+8) for all 128 rows.
//   Lane l handles rows [l*4, l*4+4) as 2 f32x2 pairs.
// ---------------------------------------------------------------------------
#define ROWS_BLK 128
#define TPB      256
#define XSTRIDE  132   // multiple of 4 -> 16B-aligned LDS.128 row loads
#define SMEM_BYTES (64 * 64 * 2 * 4 + NCH * XSTRIDE * 4)   // 32768 + 32736 = 65504

__global__ void __launch_bounds__(TPB)
encode_kernel(const float* __restrict__ market, float* __restrict__ out) {
    extern __shared__ float sm[];
    float2* sw = (float2*)sm;               // [64 cin][64 o], duplicated (w,w) pairs
    float*  sx = sm + 64 * 64 * 2;          // [62 c][132 pad] transposed market tile

    const long long row0 = (long long)blockIdx.x * ROWS_BLK;
    const float* src = market + row0 * NCH;

    // stage W (duplicated pairs) and transposed market tile
    for (int i = threadIdx.x; i < 64 * 64; i += TPB) {
        float w = g_W[i];
        sw[i] = make_float2(w, w);
    }
    for (int i = threadIdx.x; i < ROWS_BLK * NCH; i += TPB) {   // 31 exact iters
        int r = i / NCH;
        int c = i - r * NCH;
        sx[c * XSTRIDE + r] = src[i];
    }
    __syncthreads();

    const int warp = threadIdx.x >> 5;
    const int lane = threadIdx.x & 31;
    const int o0 = warp << 3;      // 8 outputs per warp (uniform across warp)
    const int r0 = lane << 2;      // 4 rows per lane

    // block never crosses a symbol boundary (8192 % 128 == 0)
    const float fs  = (float)(row0 >> 13);
    const float ft0 = (float)((int)(row0 & (NSTEPS - 1)) + r0);

    unsigned long long acc0[8], acc1[8];
#pragma unroll
    for (int j = 0; j < 8; j++) {
        float a = sw[o0 + j].x;          // cin = 0 (symbol)
        float b = sw[64 + o0 + j].x;     // cin = 1 (t)
        float base = a * fs;
        acc0[j] = pack2(base + b * ft0,          base + b * (ft0 + 1.0f));
        acc1[j] = pack2(base + b * (ft0 + 2.0f), base + b * (ft0 + 3.0f));
    }

    // market channels map to cin = 2..63
    const float2* swm = sw + 2 * 64;

#pragma unroll 2
    for (int c = 0; c < NCH; c++) {
        // 4 rows of x: one LDS.128, lanes contiguous -> conflict-free
        ulonglong2 x = *(const ulonglong2*)(sx + c * XSTRIDE + r0);
        // 8 duplicated weight pairs: 4 broadcast LDS.128 (warp-uniform address)
        const ulonglong2* wp = (const ulonglong2*)(swm + c * 64 + o0);
        ulonglong2 w0 = wp[0];
        ulonglong2 w1 = wp[1];
        ulonglong2 w2 = wp[2];
        ulonglong2 w3 = wp[3];
        acc0[0] = fma2(x.x, w0.x, acc0[0]);  acc1[0] = fma2(x.y, w0.x, acc1[0]);
        acc0[1] = fma2(x.x, w0.y, acc0[1]);  acc1[1] = fma2(x.y, w0.y, acc1[1]);
        acc0[2] = fma2(x.x, w1.x, acc0[2]);  acc1[2] = fma2(x.y, w1.x, acc1[2]);
        acc0[3] = fma2(x.x, w1.y, acc0[3]);  acc1[3] = fma2(x.y, w1.y, acc1[3]);
        acc0[4] = fma2(x.x, w2.x, acc0[4]);  acc1[4] = fma2(x.y, w2.x, acc1[4]);
        acc0[5] = fma2(x.x, w2.y, acc0[5]);  acc1[5] = fma2(x.y, w2.y, acc1[5]);
        acc0[6] = fma2(x.x, w3.x, acc0[6]);  acc1[6] = fma2(x.y, w3.x, acc1[6]);
        acc0[7] = fma2(x.x, w3.y, acc0[7]);  acc1[7] = fma2(x.y, w3.y, acc1[7]);
    }

    // store: 4 rows x 8 outs -> 2 STG.128 per row
    float* orow = out + (row0 + r0) * 64 + o0;
    {
        float v0, v1, v2, v3, v4, v5, v6, v7;
        // row r0 (lo of acc0), row r0+1 (hi of acc0)
        float4 a, b;
#pragma unroll
        for (int half = 0; half < 2; half++) {
            float* dst0 = orow + (long long)half * 128;        // rows r0+2*half, r0+2*half+1
            unsigned long long* A = half ? acc1 : acc0;
            unpack2(A[0], v0, v4); unpack2(A[1], v1, v5);
            unpack2(A[2], v2, v6); unpack2(A[3], v3, v7);
            a = make_float4(v0, v1, v2, v3);
            b = make_float4(v4, v5, v6, v7);
            *(float4*)(dst0)          = a;
            *(float4*)(dst0 + 64)     = b;
            unpack2(A[4], v0, v4); unpack2(A[5], v1, v5);
            unpack2(A[6], v2, v6); unpack2(A[7], v3, v7);
            a = make_float4(v0, v1, v2, v3);
            b = make_float4(v4, v5, v6, v7);
            *(float4*)(dst0 + 4)      = a;
            *(float4*)(dst0 + 64 + 4) = b;
        }
    }
}

// ---------------------------------------------------------------------------
extern "C" void kernel_launch(void* const* d_in, const int* in_sizes, int n_in,
                              void* d_out, int out_size) {
    const float* market = (const float*)d_in[0];
    build_weff<<<1, 256>>>((const float*)d_in[1], (const float*)d_in[2],
                           (const float*)d_in[3], (const float*)d_in[4],
                           (const float*)d_in[5], (const float*)d_in[6]);

    cudaFuncSetAttribute((const void*)encode_kernel,
                         cudaFuncAttributeMaxDynamicSharedMemorySize, SMEM_BYTES);
    const int nblocks = (NSYMS * NSTEPS) / ROWS_BLK;  // 16384
    encode_kernel<<<nblocks, TPB, SMEM_BYTES>>>(market, (float*)d_out);
}

// round 3
// speedup vs baseline: 3.3917x; 1.0638x over previous
#include <cuda_runtime.h>
#include <cstdint>

#define NSYMS  256
#define NSTEPS 8192
#define NCH    62
#define NOUT   64
#define HID    16

// Doubled effective weight: g_W2[c*32 + p] = (w[2p], w[2p+1], w[2p+1], w[2p])
// where w[o] = (W3@W2@W1)[o][c],  c = cin 0..63 (0=symbol, 1=t, 2..63=market)
__device__ float4 g_W2[64 * 32];

// ---------------------------------------------------------------------------
// Kernel 1: build W_eff = W3 @ W2 @ W1 and emit doubled layout (tiny)
// ---------------------------------------------------------------------------
__global__ void build_weff(const float* __restrict__ W1h, const float* __restrict__ M1h,
                           const float* __restrict__ W2h, const float* __restrict__ M2h,
                           const float* __restrict__ W3h, const float* __restrict__ M3h) {
    __shared__ float W1[HID * 64];
    __shared__ float W2[HID * HID];
    __shared__ float W3[64 * HID];
    __shared__ float T2[HID * 64];
    __shared__ float Wt[64 * 64];   // [c][o]
    const int tid = threadIdx.x;

    for (int i = tid; i < HID * 64; i += 256)
        W1[i] = tanhf(W1h[i]) * (1.0f / (1.0f + expf(-M1h[i])));
    for (int i = tid; i < HID * HID; i += 256)
        W2[i] = tanhf(W2h[i]) * (1.0f / (1.0f + expf(-M2h[i])));
    for (int i = tid; i < 64 * HID; i += 256)
        W3[i] = tanhf(W3h[i]) * (1.0f / (1.0f + expf(-M3h[i])));
    __syncthreads();

    for (int i = tid; i < HID * 64; i += 256) {
        int h = i >> 6, c = i & 63;
        float s = 0.0f;
#pragma unroll
        for (int k = 0; k < HID; k++) s += W2[h * HID + k] * W1[k * 64 + c];
        T2[i] = s;
    }
    __syncthreads();

    for (int i = tid; i < 64 * 64; i += 256) {
        int o = i >> 6, c = i & 63;
        float s = 0.0f;
#pragma unroll
        for (int k = 0; k < HID; k++) s += W3[o * HID + k] * T2[k * 64 + c];
        Wt[c * 64 + o] = s;
    }
    __syncthreads();

    for (int i = tid; i < 64 * 32; i += 256) {
        int c = i >> 5, p = i & 31;
        float a = Wt[c * 64 + 2 * p];
        float b = Wt[c * 64 + 2 * p + 1];
        g_W2[i] = make_float4(a, b, b, a);
    }
}

// ---------------------------------------------------------------------------
// Packed fp32x2 helpers
// ---------------------------------------------------------------------------
typedef unsigned long long ull;
__device__ __forceinline__ ull fma2(ull a, ull b, ull c) {
    ull d;
    asm("fma.rn.f32x2 %0, %1, %2, %3;" : "=l"(d) : "l"(a), "l"(b), "l"(c));
    return d;
}
__device__ __forceinline__ ull pack2(float lo, float hi) {
    ull r;
    asm("mov.b64 %0, {%1, %2};" : "=l"(r) : "f"(lo), "f"(hi));
    return r;
}
__device__ __forceinline__ void unpack2(ull v, float& lo, float& hi) {
    asm("mov.b64 {%0, %1}, %2;" : "=f"(lo), "=f"(hi) : "l"(v));
}

// ---------------------------------------------------------------------------
// Kernel 2: diagonal-paired fp32x2 GEMM.
//   Block: 256 threads = 8 warps, 256 rows. Warp owns 32 private rows x 64 outs.
//   Lane = rg*16 + og:  rows [warp*32 + rg*16, +16),  outs [og*4, og*4+4).
//   acc A[rp][op] = (out 2j @ row r,  out 2j+1 @ row r+1)   (diagonal)
//   acc B[rp][op] = (out 2j+1 @ row r, out 2j @ row r+1)    (anti-diagonal)
//   -> fma2 operands are natural pairs: x=(x_r,x_{r+1}), w=(w_2j,w_2j+1)/swapped.
// ---------------------------------------------------------------------------
#define ROWS_BLK 256
#define TPB      256
#define XSTRIDE  260   // mult of 4 (16B-aligned LDS.128); 260%32=4 -> 4-way staging conflicts only
#define SW_BYTES (64 * 32 * 16)            // 32768
#define SX_BYTES (NCH * XSTRIDE * 4)       // 64480
#define SMEM_BYTES (SW_BYTES + SX_BYTES)   // 97248

__global__ void __launch_bounds__(TPB, 2)
encode_kernel(const float* __restrict__ market, float* __restrict__ out) {
    extern __shared__ float sm[];
    float4* sw = (float4*)sm;                  // [64 c][32 outpairs] (diag, swapped)
    float*  sx = sm + 64 * 32 * 4;             // [62 c][260 pad] transposed tile

    const long long row0 = (long long)blockIdx.x * ROWS_BLK;
    const float* src = market + row0 * NCH;

    // stage doubled weights (conflict-free) and transposed market tile
    for (int i = threadIdx.x; i < 64 * 32; i += TPB)
        sw[i] = g_W2[i];
    for (int i = threadIdx.x; i < ROWS_BLK * NCH; i += TPB) {   // 62 exact iters
        int r = i / NCH;
        int c = i - r * NCH;
        sx[c * XSTRIDE + r] = src[i];
    }
    __syncthreads();

    const int warp = threadIdx.x >> 5;
    const int lane = threadIdx.x & 31;
    const int rg = lane >> 4;            // 0..1
    const int og = lane & 15;            // 0..15
    const int r0 = warp * 32 + rg * 16;  // 16 rows per thread
    const int op0 = og * 2;              // 2 outpairs -> outs [4og, 4og+4)

    // ---- init: acc = s*w0 + t*w1  (cin 0,1), 8192 % 256 == 0 -> one symbol/block
    const float fs  = (float)(row0 >> 13);
    const float ft0 = (float)((int)(row0 & (NSTEPS - 1)) + r0);
    const ull sv = pack2(fs, fs);

    ull A0[8], B0[8], A1[8], B1[8];   // [rowpair], outpair 0 / 1
    {
        const ulonglong2* w0 = (const ulonglong2*)(sw + op0);        // c=0
        const ulonglong2* w1 = (const ulonglong2*)(sw + 32 + op0);   // c=1
        ulonglong2 w0a = w0[0], w0b = w0[1];
        ulonglong2 w1a = w1[0], w1b = w1[1];
#pragma unroll
        for (int rp = 0; rp < 8; rp++) {
            ull tv = pack2(ft0 + (float)(2 * rp), ft0 + (float)(2 * rp + 1));
            A0[rp] = fma2(sv, w0a.x, fma2(tv, w1a.x, 0ULL));
            B0[rp] = fma2(sv, w0a.y, fma2(tv, w1a.y, 0ULL));
            A1[rp] = fma2(sv, w0b.x, fma2(tv, w1b.x, 0ULL));
            B1[rp] = fma2(sv, w0b.y, fma2(tv, w1b.y, 0ULL));
        }
    }

    // ---- main loop over 62 market channels (cin 2..63)
    const float* xc = sx + r0;
    const ulonglong2* wc = (const ulonglong2*)(sw + 2 * 32) + op0;

#pragma unroll 2
    for (int c = 0; c < NCH; c++) {
        ulonglong2 xv0 = *(const ulonglong2*)(xc);        // rows r0..r0+3
        ulonglong2 xv1 = *(const ulonglong2*)(xc + 4);
        ulonglong2 xv2 = *(const ulonglong2*)(xc + 8);
        ulonglong2 xv3 = *(const ulonglong2*)(xc + 12);
        ulonglong2 wa = wc[0];   // (diag pair, swapped pair) outpair op0
        ulonglong2 wb = wc[1];   // outpair op0+1
        xc += XSTRIDE;
        wc += 32;

        ull xs[8] = {xv0.x, xv0.y, xv1.x, xv1.y, xv2.x, xv2.y, xv3.x, xv3.y};
#pragma unroll
        for (int rp = 0; rp < 8; rp++) {
            A0[rp] = fma2(xs[rp], wa.x, A0[rp]);
            B0[rp] = fma2(xs[rp], wa.y, B0[rp]);
            A1[rp] = fma2(xs[rp], wb.x, A1[rp]);
            B1[rp] = fma2(xs[rp], wb.y, B1[rp]);
        }
    }

    // ---- epilogue: un-diagonalize and store coalesced STG.128
    // row even (r = r0+2rp):   (A0.lo, B0.lo, A1.lo, B1.lo)
    // row odd  (r = r0+2rp+1): (B0.hi, A0.hi, B1.hi, A1.hi)
    float* obase = out + (row0 + r0) * 64 + og * 4;
#pragma unroll
    for (int rp = 0; rp < 8; rp++) {
        float a0l, a0h, b0l, b0h, a1l, a1h, b1l, b1h;
        unpack2(A0[rp], a0l, a0h);
        unpack2(B0[rp], b0l, b0h);
        unpack2(A1[rp], a1l, a1h);
        unpack2(B1[rp], b1l, b1h);
        *(float4*)(obase + (2 * rp) * 64)     = make_float4(a0l, b0l, a1l, b1l);
        *(float4*)(obase + (2 * rp + 1) * 64) = make_float4(b0h, a0h, b1h, a1h);
    }
}

// ---------------------------------------------------------------------------
extern "C" void kernel_launch(void* const* d_in, const int* in_sizes, int n_in,
                              void* d_out, int out_size) {
    const float* market = (const float*)d_in[0];
    build_weff<<<1, 256>>>((const float*)d_in[1], (const float*)d_in[2],
                           (const float*)d_in[3], (const float*)d_in[4],
                           (const float*)d_in[5], (const float*)d_in[6]);

    cudaFuncSetAttribute((const void*)encode_kernel,
                         cudaFuncAttributeMaxDynamicSharedMemorySize, SMEM_BYTES);
    const int nblocks = (NSYMS * NSTEPS) / ROWS_BLK;  // 8192
    encode_kernel<<<nblocks, TPB, SMEM_BYTES>>>(market, (float*)d_out);
}

// round 5
// speedup vs baseline: 7.3560x; 2.1688x over previous
#include <cuda_runtime.h>
#include <cuda_bf16.h>
#include <cstdint>

#define NSYMS  256
#define NSTEPS 8192
#define NCH    62
#define HID    16

// ===========================================================================
// Pre-packed B fragments for mma.m16n8k16:
//   g_Bfrag[(ks*8+nt)*32 + lane] = { bh0, bh1, bl0, bl1 }
//   where for lane (g=lane/4, q=lane%4), n = nt*8+g, k0 = ks*16+2q:
//     b*0 = bf16x2( w(k0), w(k0+1) ), b*1 = bf16x2( w(k0+8), w(k0+9) )
//   w(k): k 0..61 -> market cin k+2; k=62 -> sym (cin 0); k=63 -> t (cin 1)
// ===========================================================================
__device__ uint4 g_Bfrag[4 * 8 * 32];

__global__ void build_weff(const float* __restrict__ W1h, const float* __restrict__ M1h,
                           const float* __restrict__ W2h, const float* __restrict__ M2h,
                           const float* __restrict__ W3h, const float* __restrict__ M3h) {
    __shared__ float W1[HID * 64];
    __shared__ float W2[HID * HID];
    __shared__ float W3[64 * HID];
    __shared__ float T2[HID * 64];
    __shared__ float Wt[64 * 64];   // [cin][o]
    const int tid = threadIdx.x;

    for (int i = tid; i < HID * 64; i += 256)
        W1[i] = tanhf(W1h[i]) * (1.0f / (1.0f + expf(-M1h[i])));
    for (int i = tid; i < HID * HID; i += 256)
        W2[i] = tanhf(W2h[i]) * (1.0f / (1.0f + expf(-M2h[i])));
    for (int i = tid; i < 64 * HID; i += 256)
        W3[i] = tanhf(W3h[i]) * (1.0f / (1.0f + expf(-M3h[i])));
    __syncthreads();

    for (int i = tid; i < HID * 64; i += 256) {
        int h = i >> 6, c = i & 63;
        float s = 0.0f;
#pragma unroll
        for (int k = 0; k < HID; k++) s += W2[h * HID + k] * W1[k * 64 + c];
        T2[i] = s;
    }
    __syncthreads();

    for (int i = tid; i < 64 * 64; i += 256) {
        int o = i >> 6, c = i & 63;
        float s = 0.0f;
#pragma unroll
        for (int k = 0; k < HID; k++) s += W3[o * HID + k] * T2[k * 64 + c];
        Wt[c * 64 + o] = s;
    }
    __syncthreads();

    for (int i = tid; i < 1024; i += 256) {
        int lane = i & 31, nt = (i >> 5) & 7, ks = i >> 8;
        int g = lane >> 2, q = lane & 3;
        int n = nt * 8 + g;
        int k0 = ks * 16 + 2 * q;

        float w[4];
#pragma unroll
        for (int j = 0; j < 4; j++) {
            int k = k0 + (j >> 1) * 8 + (j & 1);
            int cin = (k < 62) ? (k + 2) : (k - 62);
            w[j] = Wt[cin * 64 + n];
        }
        float wh[4], wl[4];
#pragma unroll
        for (int j = 0; j < 4; j++) {
            __nv_bfloat16 b = __float2bfloat16(w[j]);
            wh[j] = __bfloat162float(b);
            wl[j] = w[j] - wh[j];
        }
        __nv_bfloat162 h01 = __floats2bfloat162_rn(wh[0], wh[1]);  // .x=lo(k0)
        __nv_bfloat162 h89 = __floats2bfloat162_rn(wh[2], wh[3]);
        __nv_bfloat162 l01 = __floats2bfloat162_rn(wl[0], wl[1]);
        __nv_bfloat162 l89 = __floats2bfloat162_rn(wl[2], wl[3]);
        uint4 u;
        u.x = *reinterpret_cast<uint32_t*>(&h01);
        u.y = *reinterpret_cast<uint32_t*>(&h89);
        u.z = *reinterpret_cast<uint32_t*>(&l01);
        u.w = *reinterpret_cast<uint32_t*>(&l89);
        g_Bfrag[i] = u;
    }
}

// ===========================================================================
// mma.sync m16n8k16 bf16 (sm_80+ PTX, valid on compute_103 family target)
// ===========================================================================
__device__ __forceinline__ void mma16816(float& d0, float& d1, float& d2, float& d3,
                                         uint32_t a0, uint32_t a1, uint32_t a2, uint32_t a3,
                                         uint32_t b0, uint32_t b1) {
    asm volatile("mma.sync.aligned.m16n8k16.row.col.f32.bf16.bf16.f32 "
                 "{%0,%1,%2,%3}, {%4,%5,%6,%7}, {%8,%9}, {%0,%1,%2,%3};"
                 : "+f"(d0), "+f"(d1), "+f"(d2), "+f"(d3)
                 : "r"(a0), "r"(a1), "r"(a2), "r"(a3), "r"(b0), "r"(b1));
}

// split two fp32 into bf16x2 hi (rn) + bf16x2 lo residual (rn)
__device__ __forceinline__ void cvt_split(float x, float y, uint32_t& h, uint32_t& l) {
    asm("cvt.rn.bf16x2.f32 %0, %1, %2;" : "=r"(h) : "f"(y), "f"(x));  // lo=x, hi=y
    uint32_t hxb = h << 16;
    uint32_t hyb = h & 0xFFFF0000u;
    float lx = x - __uint_as_float(hxb);
    float ly = y - __uint_as_float(hyb);
    asm("cvt.rn.bf16x2.f32 %0, %1, %2;" : "=r"(l) : "f"(ly), "f"(lx));
}

// ===========================================================================
// Main kernel: pure-register split-bf16 tensor GEMM.
//   CTA: 256 threads = 8 warps; warp = 16 rows x 64 outs; 4 iters -> 512 rows.
// ===========================================================================
#define ITERS 4

__global__ void __launch_bounds__(256, 1)
encode_kernel(const float* __restrict__ market, float* __restrict__ out) {
    const int tid  = threadIdx.x;
    const int warp = tid >> 5;
    const int lane = tid & 31;
    const int g = lane >> 2;     // 0..7
    const int q = lane & 3;      // 0..3

    // ---- B fragments: 128 regs, loaded once (coalesced LDG.128, L2-hot)
    uint32_t BH0[32], BH1[32], BL0[32], BL1[32];
#pragma unroll
    for (int i = 0; i < 32; i++) {
        uint4 u = g_Bfrag[i * 32 + lane];
        BH0[i] = u.x; BH1[i] = u.y; BL0[i] = u.z; BL1[i] = u.w;
    }

    const long long cta_row0 = (long long)blockIdx.x * (128 * ITERS);
    const float sval = (float)(cta_row0 >> 13);
    const int   tcta = (int)(cta_row0 & (NSTEPS - 1));

#pragma unroll 1
    for (int it = 0; it < ITERS; it++) {
        const int rloc = it * 128 + warp * 16 + g;       // local row of "g" lane-row
        const long long grow = cta_row0 + rloc;
        const float* p0 = market + (long long)grow * NCH;
        const float* p1 = p0 + 8 * NCH;

        // ---- load this thread's 32 A-fragment scalars
        float v[32];
#pragma unroll
        for (int ks = 0; ks < 4; ks++) {
            const int c0 = ks * 16 + 2 * q;
            const int c1 = (ks == 3 && q == 3) ? 0 : (c0 + 8);   // guard col 62/63
            v[ks * 8 + 0] = p0[c0];     v[ks * 8 + 1] = p0[c0 + 1];
            v[ks * 8 + 2] = p0[c1];     v[ks * 8 + 3] = p0[c1 + 1];
            v[ks * 8 + 4] = p1[c0];     v[ks * 8 + 5] = p1[c0 + 1];
            v[ks * 8 + 6] = p1[c1];     v[ks * 8 + 7] = p1[c1 + 1];
        }
        if (q == 3) {   // cols 62,63 = (sym, t)
            float tg = (float)(tcta + rloc);
            v[26] = sval; v[27] = tg;
            v[30] = sval; v[31] = tg + 8.0f;
        }

        float acc[32];
#pragma unroll
        for (int i = 0; i < 32; i++) acc[i] = 0.0f;

#pragma unroll
        for (int ks = 0; ks < 4; ks++) {
            uint32_t ah0, ah1, ah2, ah3, al0, al1, al2, al3;
            cvt_split(v[ks * 8 + 0], v[ks * 8 + 1], ah0, al0);   // row g,   k-pair 0
            cvt_split(v[ks * 8 + 4], v[ks * 8 + 5], ah1, al1);   // row g+8, k-pair 0
            cvt_split(v[ks * 8 + 2], v[ks * 8 + 3], ah2, al2);   // row g,   k-pair 1
            cvt_split(v[ks * 8 + 6], v[ks * 8 + 7], ah3, al3);   // row g+8, k-pair 1
#pragma unroll
            for (int nt = 0; nt < 8; nt++) {
                const int bi = ks * 8 + nt;
                mma16816(acc[nt*4+0], acc[nt*4+1], acc[nt*4+2], acc[nt*4+3],
                         ah0, ah1, ah2, ah3, BH0[bi], BH1[bi]);
                mma16816(acc[nt*4+0], acc[nt*4+1], acc[nt*4+2], acc[nt*4+3],
                         ah0, ah1, ah2, ah3, BL0[bi], BL1[bi]);
                mma16816(acc[nt*4+0], acc[nt*4+1], acc[nt*4+2], acc[nt*4+3],
                         al0, al1, al2, al3, BH0[bi], BH1[bi]);
            }
        }

        // ---- store D fragments: rows g / g+8, cols nt*8 + 2q
        float* o0 = out + (long long)grow * 64 + 2 * q;
        float* o1 = o0 + 8 * 64;
#pragma unroll
        for (int nt = 0; nt < 8; nt++) {
            *(float2*)(o0 + nt * 8) = make_float2(acc[nt*4+0], acc[nt*4+1]);
            *(float2*)(o1 + nt * 8) = make_float2(acc[nt*4+2], acc[nt*4+3]);
        }
    }
}

// ---------------------------------------------------------------------------
extern "C" void kernel_launch(void* const* d_in, const int* in_sizes, int n_in,
                              void* d_out, int out_size) {
    const float* market = (const float*)d_in[0];
    build_weff<<<1, 256>>>((const float*)d_in[1], (const float*)d_in[2],
                           (const float*)d_in[3], (const float*)d_in[4],
                           (const float*)d_in[5], (const float*)d_in[6]);

    const int nblocks = (NSYMS * NSTEPS) / (128 * ITERS);   // 4096
    encode_kernel<<<nblocks, 256>>>(market, (float*)d_out);
}

// round 6
// speedup vs baseline: 9.3528x; 1.2715x over previous
#include <cuda_runtime.h>
#include <cuda_bf16.h>
#include <cstdint>

#define NSYMS  256
#define NSTEPS 8192
#define NCH    62
#define HID    16

// ===========================================================================
// Pre-packed B fragments for mma.m16n8k16:
//   g_Bfrag[(ks*8+nt)*32 + lane] = { bh0, bh1, bl0, bl1 }
//   lane (g=lane/4, q=lane%4), n = nt*8+g, k0 = ks*16+2q:
//     b*0 = bf16x2( w(k0), w(k0+1) ), b*1 = bf16x2( w(k0+8), w(k0+9) )
//   w(k): k 0..61 -> market cin k+2; k=62 -> sym (cin 0); k=63 -> t (cin 1)
// ===========================================================================
__device__ uint4 g_Bfrag[4 * 8 * 32];

__global__ void build_weff(const float* __restrict__ W1h, const float* __restrict__ M1h,
                           const float* __restrict__ W2h, const float* __restrict__ M2h,
                           const float* __restrict__ W3h, const float* __restrict__ M3h) {
    __shared__ float W1[HID * 64];
    __shared__ float W2[HID * HID];
    __shared__ float W3[64 * HID];
    __shared__ float T2[HID * 64];
    __shared__ float Wt[64 * 64];   // [cin][o]
    const int tid = threadIdx.x;

    for (int i = tid; i < HID * 64; i += 256)
        W1[i] = tanhf(W1h[i]) * (1.0f / (1.0f + expf(-M1h[i])));
    for (int i = tid; i < HID * HID; i += 256)
        W2[i] = tanhf(W2h[i]) * (1.0f / (1.0f + expf(-M2h[i])));
    for (int i = tid; i < 64 * HID; i += 256)
        W3[i] = tanhf(W3h[i]) * (1.0f / (1.0f + expf(-M3h[i])));
    __syncthreads();

    for (int i = tid; i < HID * 64; i += 256) {
        int h = i >> 6, c = i & 63;
        float s = 0.0f;
#pragma unroll
        for (int k = 0; k < HID; k++) s += W2[h * HID + k] * W1[k * 64 + c];
        T2[i] = s;
    }
    __syncthreads();

    for (int i = tid; i < 64 * 64; i += 256) {
        int o = i >> 6, c = i & 63;
        float s = 0.0f;
#pragma unroll
        for (int k = 0; k < HID; k++) s += W3[o * HID + k] * T2[k * 64 + c];
        Wt[c * 64 + o] = s;
    }
    __syncthreads();

    for (int i = tid; i < 1024; i += 256) {
        int lane = i & 31, nt = (i >> 5) & 7, ks = i >> 8;
        int g = lane >> 2, q = lane & 3;
        int n = nt * 8 + g;
        int k0 = ks * 16 + 2 * q;

        float w[4];
#pragma unroll
        for (int j = 0; j < 4; j++) {
            int k = k0 + (j >> 1) * 8 + (j & 1);
            int cin = (k < 62) ? (k + 2) : (k - 62);
            w[j] = Wt[cin * 64 + n];
        }
        float wh[4], wl[4];
#pragma unroll
        for (int j = 0; j < 4; j++) {
            __nv_bfloat16 b = __float2bfloat16(w[j]);
            wh[j] = __bfloat162float(b);
            wl[j] = w[j] - wh[j];
        }
        __nv_bfloat162 h01 = __floats2bfloat162_rn(wh[0], wh[1]);
        __nv_bfloat162 h89 = __floats2bfloat162_rn(wh[2], wh[3]);
        __nv_bfloat162 l01 = __floats2bfloat162_rn(wl[0], wl[1]);
        __nv_bfloat162 l89 = __floats2bfloat162_rn(wl[2], wl[3]);
        uint4 u;
        u.x = *reinterpret_cast<uint32_t*>(&h01);
        u.y = *reinterpret_cast<uint32_t*>(&h89);
        u.z = *reinterpret_cast<uint32_t*>(&l01);
        u.w = *reinterpret_cast<uint32_t*>(&l89);
        g_Bfrag[i] = u;
    }
}

// ===========================================================================
// PTX helpers
// ===========================================================================
__device__ __forceinline__ void mma16816(float& d0, float& d1, float& d2, float& d3,
                                         uint32_t a0, uint32_t a1, uint32_t a2, uint32_t a3,
                                         uint32_t b0, uint32_t b1) {
    asm volatile("mma.sync.aligned.m16n8k16.row.col.f32.bf16.bf16.f32 "
                 "{%0,%1,%2,%3}, {%4,%5,%6,%7}, {%8,%9}, {%0,%1,%2,%3};"
                 : "+f"(d0), "+f"(d1), "+f"(d2), "+f"(d3)
                 : "r"(a0), "r"(a1), "r"(a2), "r"(a3), "r"(b0), "r"(b1));
}

__device__ __forceinline__ void cvt_split(float x, float y, uint32_t& h, uint32_t& l) {
    asm("cvt.rn.bf16x2.f32 %0, %1, %2;" : "=r"(h) : "f"(y), "f"(x));  // lo=x, hi=y
    uint32_t hxb = h << 16;
    uint32_t hyb = h & 0xFFFF0000u;
    float lx = x - __uint_as_float(hxb);
    float ly = y - __uint_as_float(hyb);
    asm("cvt.rn.bf16x2.f32 %0, %1, %2;" : "=r"(l) : "f"(ly), "f"(lx));
}

__device__ __forceinline__ uint32_t smem_u32(const void* p) {
    uint32_t a;
    asm("{ .reg .u64 t; cvta.to.shared.u64 t, %1; cvt.u32.u64 %0, t; }" : "=r"(a) : "l"(p));
    return a;
}
#define STS64F(a, f0, f1) \
    asm volatile("st.shared.v2.f32 [%0], {%1, %2};" :: "r"(a), "f"(f0), "f"(f1) : "memory")
#define LDS128F(f0, f1, f2, f3, a) \
    asm volatile("ld.shared.v4.f32 {%0, %1, %2, %3}, [%4];" : "=f"(f0), "=f"(f1), "=f"(f2), "=f"(f3) : "r"(a))

// ===========================================================================
// Main kernel: register-resident split-bf16 tensor GEMM.
//   CTA: 256 threads = 8 warps; warp = 16 rows x 64 outs; ITERS=4 -> 512 rows.
//   Epilogue: per-warp XOR-swizzled smem tile -> coalesced STG.128.
// ===========================================================================
#define ITERS 4

__global__ void __launch_bounds__(256, 1)
encode_kernel(const float* __restrict__ market, float* __restrict__ out) {
    __shared__ float sepi[8 * 16 * 64];   // 32KB: per-warp 16x64 D tile (swizzled)

    const int tid  = threadIdx.x;
    const int warp = tid >> 5;
    const int lane = tid & 31;
    const int g = lane >> 2;     // 0..7
    const int q = lane & 3;      // 0..3

    // ---- B fragments: 128 regs, loaded once
    uint32_t BH0[32], BH1[32], BL0[32], BL1[32];
#pragma unroll
    for (int i = 0; i < 32; i++) {
        uint4 u = g_Bfrag[i * 32 + lane];
        BH0[i] = u.x; BH1[i] = u.y; BL0[i] = u.z; BL1[i] = u.w;
    }

    const long long cta_row0 = (long long)blockIdx.x * (128 * ITERS);
    const float sval = (float)(cta_row0 >> 13);
    const int   tcta = (int)(cta_row0 & (NSTEPS - 1));

    const uint32_t wb = smem_u32(sepi) + warp * 4096;   // per-warp 4KB tile

    // v layout per iter: [ks*4 + {p0 pair0, p0 pair1, p1 pair0, p1 pair1}]
    float2 vc[16], vn[16];

    // ---- preload iter 0
    {
        const int rloc = warp * 16 + g;
        const float* p0 = market + (cta_row0 + rloc) * NCH;
        const float* p1 = p0 + 8 * NCH;
#pragma unroll
        for (int ks = 0; ks < 4; ks++) {
            const int c0 = ks * 16 + 2 * q;
            vc[ks * 4 + 0] = *(const float2*)(p0 + c0);
            vc[ks * 4 + 2] = *(const float2*)(p1 + c0);
            if (ks == 3 && q == 3) {
                float tg = (float)(tcta + rloc);
                vc[13] = make_float2(sval, tg);
                vc[15] = make_float2(sval, tg + 8.0f);
            } else {
                vc[ks * 4 + 1] = *(const float2*)(p0 + c0 + 8);
                vc[ks * 4 + 3] = *(const float2*)(p1 + c0 + 8);
            }
        }
    }

#pragma unroll 1
    for (int it = 0; it < ITERS; it++) {
        // ---- prefetch next iter (overlaps with MMAs below)
        if (it + 1 < ITERS) {
            const int rloc = (it + 1) * 128 + warp * 16 + g;
            const float* p0 = market + (cta_row0 + rloc) * NCH;
            const float* p1 = p0 + 8 * NCH;
#pragma unroll
            for (int ks = 0; ks < 4; ks++) {
                const int c0 = ks * 16 + 2 * q;
                vn[ks * 4 + 0] = *(const float2*)(p0 + c0);
                vn[ks * 4 + 2] = *(const float2*)(p1 + c0);
                if (ks == 3 && q == 3) {
                    float tg = (float)(tcta + rloc);
                    vn[13] = make_float2(sval, tg);
                    vn[15] = make_float2(sval, tg + 8.0f);
                } else {
                    vn[ks * 4 + 1] = *(const float2*)(p0 + c0 + 8);
                    vn[ks * 4 + 3] = *(const float2*)(p1 + c0 + 8);
                }
            }
        }

        // ---- convert + MMA
        float acc[32];
#pragma unroll
        for (int i = 0; i < 32; i++) acc[i] = 0.0f;

#pragma unroll
        for (int ks = 0; ks < 4; ks++) {
            uint32_t ah0, ah1, ah2, ah3, al0, al1, al2, al3;
            cvt_split(vc[ks*4+0].x, vc[ks*4+0].y, ah0, al0);   // row g,   pair0
            cvt_split(vc[ks*4+2].x, vc[ks*4+2].y, ah1, al1);   // row g+8, pair0
            cvt_split(vc[ks*4+1].x, vc[ks*4+1].y, ah2, al2);   // row g,   pair1
            cvt_split(vc[ks*4+3].x, vc[ks*4+3].y, ah3, al3);   // row g+8, pair1
#pragma unroll
            for (int nt = 0; nt < 8; nt++) {
                const int bi = ks * 8 + nt;
                mma16816(acc[nt*4+0], acc[nt*4+1], acc[nt*4+2], acc[nt*4+3],
                         ah0, ah1, ah2, ah3, BH0[bi], BH1[bi]);
                mma16816(acc[nt*4+0], acc[nt*4+1], acc[nt*4+2], acc[nt*4+3],
                         ah0, ah1, ah2, ah3, BL0[bi], BL1[bi]);
                mma16816(acc[nt*4+0], acc[nt*4+1], acc[nt*4+2], acc[nt*4+3],
                         al0, al1, al2, al3, BH0[bi], BH1[bi]);
            }
        }

        // ---- epilogue: fragments -> swizzled smem -> coalesced STG.128
        // smem tile: row-major 16 rows x 64 floats; float4-granule XOR swizzle:
        //   phys_f4 = logical_f4 ^ row
        {
            const int qhi = q >> 1, qlo = q & 1;
#pragma unroll
            for (int nt = 0; nt < 8; nt++) {
                uint32_t f4a = (uint32_t)((2 * nt + qhi) ^ g);
                uint32_t f4b = (uint32_t)((2 * nt + qhi) ^ (g + 8));
                STS64F(wb + g * 256 + f4a * 16 + qlo * 8,      acc[nt*4+0], acc[nt*4+1]);
                STS64F(wb + (g + 8) * 256 + f4b * 16 + qlo * 8, acc[nt*4+2], acc[nt*4+3]);
            }
        }
        __syncwarp();

        {
            float* obase = out + (cta_row0 + (long long)it * 128 + warp * 16) * 64;
#pragma unroll
            for (int i = 0; i < 8; i++) {
                int slot = i * 32 + lane;
                int row = slot >> 4;
                int c4 = slot & 15;
                uint32_t f4 = (uint32_t)(c4 ^ row);
                float f0, f1, f2, f3;
                LDS128F(f0, f1, f2, f3, wb + row * 256 + f4 * 16);
                *(float4*)(obase + row * 64 + c4 * 4) = make_float4(f0, f1, f2, f3);
            }
        }
        __syncwarp();

        // rotate prefetch buffer
#pragma unroll
        for (int i = 0; i < 16; i++) vc[i] = vn[i];
    }
}

// ---------------------------------------------------------------------------
extern "C" void kernel_launch(void* const* d_in, const int* in_sizes, int n_in,
                              void* d_out, int out_size) {
    const float* market = (const float*)d_in[0];
    build_weff<<<1, 256>>>((const float*)d_in[1], (const float*)d_in[2],
                           (const float*)d_in[3], (const float*)d_in[4],
                           (const float*)d_in[5], (const float*)d_in[6]);

    const int nblocks = (NSYMS * NSTEPS) / (128 * ITERS);   // 4096
    encode_kernel<<<nblocks, 256>>>(market, (float*)d_out);
}